// round 10
// baseline (speedup 1.0000x reference)
#include <cuda_runtime.h>
#include <cstdint>

// Degenerate conv (reference uses only x[:,0] and w[:,2]):
//   out(n,f,i,j) = bias[f] + sum_{a,b} w[f,2,a,b] * x[n,0,i+a,j+b]
//   x: (16,3,256,256) f32, w: (64,3,3,3) f32, b: (64,) f32
//   out: (16,64,254,254) f32
//
// Structure: 1 row x 4 cols per thread, 16 filters (blockIdx.z quarter).
// All main stores are STG.128, warp-dense 512B. Out-row base is 8*i mod 16,
// so odd rows use j = 4t+2 tiles to keep 16B store alignment; even rows use
// j = 4t. The leftover 2-col strip per row is handled by lane t=63.
// Weights in __constant__ (uniform LDC port); bias via 4 uniform LDG.128.
#define NB     16
#define F_OUT  64
#define F_Q    16
#define Hh     256
#define Ww     256
#define HO     254
#define WO     254

typedef unsigned long long u64;

__constant__ float c_w[F_OUT * 27];   // full weight tensor (we use [f][2][*])

// packed f32x2 FMA (Blackwell): d = a * w + c on both lanes
static __device__ __forceinline__ u64 ffma2(u64 a, u64 w, u64 c) {
    u64 d;
    asm("fma.rn.f32x2 %0, %1, %2, %3;" : "=l"(d) : "l"(a), "l"(w), "l"(c));
    return d;
}

static __device__ __forceinline__ u64 pack2(float lo, float hi) {
    u64 d;
    asm("mov.b64 %0, {%1, %2};" : "=l"(d) : "f"(lo), "f"(hi));
    return d;
}

__global__ __launch_bounds__(128) void conv2dcq_kernel(
    const float* __restrict__ x,
    const float* __restrict__ bias,
    float* __restrict__ out) {

    const int tid = threadIdx.x;
    const int rs  = tid >> 6;             // row within row-pair (0/1), warp-uniform
    const int t   = tid & 63;             // col tile 0..63
    const int i   = blockIdx.x * 2 + rs;  // output row 0..253
    const int n   = blockIdx.y;
    const int f0  = blockIdx.z * F_Q;     // block-uniform filter base

    // bias for this quarter: 4 uniform LDG.128 (f0 multiple of 16 -> 64B aligned)
    const float4* b4 = reinterpret_cast<const float4*>(bias + f0);
    const float4 bv0 = __ldg(b4 + 0);
    const float4 bv1 = __ldg(b4 + 1);
    const float4 bv2 = __ldg(b4 + 2);
    const float4 bv3 = __ldg(b4 + 3);
    const float bvals[16] = {bv0.x, bv0.y, bv0.z, bv0.w,
                             bv1.x, bv1.y, bv1.z, bv1.w,
                             bv2.x, bv2.y, bv2.z, bv2.w,
                             bv3.x, bv3.y, bv3.z, bv3.w};

    const float* xrow = x + (size_t)n * 3 * Hh * Ww + (size_t)i * Ww;
    float* orow = out + (size_t)n * F_OUT * HO * WO
                      + (size_t)f0 * HO * WO
                      + (size_t)i * WO;

    if (t < 63) {
        // ---- main: 4 output cols at j = 4t + 2*rs (16B-aligned store) ----
        const int j = 4 * t + 2 * rs;

        // Load 3 rows x 6 input cols; rs is warp-uniform so branch is uniform.
        float v[3][6];
        #pragma unroll
        for (int r = 0; r < 3; r++) {
            const float* xr = xrow + (size_t)r * Ww + j;
            if (rs == 0) {               // j % 4 == 0: float4 then float2
                const float4 a = *reinterpret_cast<const float4*>(xr);
                const float2 b = *reinterpret_cast<const float2*>(xr + 4);
                v[r][0] = a.x; v[r][1] = a.y; v[r][2] = a.z;
                v[r][3] = a.w; v[r][4] = b.x; v[r][5] = b.y;
            } else {                     // j % 4 == 2: float2 then float4
                const float2 a = *reinterpret_cast<const float2*>(xr);
                const float4 b = *reinterpret_cast<const float4*>(xr + 2);
                v[r][0] = a.x; v[r][1] = a.y; v[r][2] = b.x;
                v[r][3] = b.y; v[r][4] = b.z; v[r][5] = b.w;
            }
        }

        // P[r][s] = (v[r][s], v[r][s+1]), s = 0..4
        u64 P[3][5];
        #pragma unroll
        for (int r = 0; r < 3; r++)
            #pragma unroll
            for (int s = 0; s < 5; s++)
                P[r][s] = pack2(v[r][s], v[r][s + 1]);

        float* ob = orow + j;

        #pragma unroll 4
        for (int fi = 0; fi < F_Q; fi++) {
            const float* wf = c_w + (f0 + fi) * 27 + 18;  // uniform LDC
            const float bv = bvals[fi];
            u64 a0 = pack2(bv, bv);     // cols j, j+1
            u64 a1 = a0;                // cols j+2, j+3

            #pragma unroll
            for (int a = 0; a < 3; a++) {
                #pragma unroll
                for (int b = 0; b < 3; b++) {
                    const float ws = wf[a * 3 + b];
                    const u64 wp = pack2(ws, ws);
                    a0 = ffma2(P[a][b],     wp, a0);
                    a1 = ffma2(P[a][b + 2], wp, a1);
                }
            }

            // 16B-aligned: (i*1016 + j*4) % 16 == 0 by construction
            *reinterpret_cast<ulonglong2*>(ob) = make_ulonglong2(a0, a1);
            ob += (size_t)HO * WO;
        }
    } else {
        // ---- tail: 2 cols at j = 252 (even rows) / j = 0 (odd rows) ----
        const int j = rs ? 0 : 252;

        u64 P[3][3];
        #pragma unroll
        for (int r = 0; r < 3; r++) {
            // 252*4 = 1008 (16B-aligned); j=0 trivially aligned
            const float4 a = *reinterpret_cast<const float4*>(xrow + (size_t)r * Ww + j);
            P[r][0] = pack2(a.x, a.y);
            P[r][1] = pack2(a.y, a.z);
            P[r][2] = pack2(a.z, a.w);
        }

        float* ob = orow + j;

        #pragma unroll 4
        for (int fi = 0; fi < F_Q; fi++) {
            const float* wf = c_w + (f0 + fi) * 27 + 18;
            const float bv = bvals[fi];
            u64 a0 = pack2(bv, bv);

            #pragma unroll
            for (int a = 0; a < 3; a++) {
                #pragma unroll
                for (int b = 0; b < 3; b++) {
                    const float ws = wf[a * 3 + b];
                    a0 = ffma2(P[a][b], pack2(ws, ws), a0);
                }
            }

            *reinterpret_cast<u64*>(ob) = a0;   // 8B-aligned
            ob += (size_t)HO * WO;
        }
    }
}

extern "C" void kernel_launch(void* const* d_in, const int* in_sizes, int n_in,
                              void* d_out, int out_size) {
    const float* x    = (const float*)d_in[0];
    const float* w    = (const float*)d_in[1];
    const float* bias = (const float*)d_in[2];
    float* out        = (float*)d_out;

    // Single CE node: stage weights into constant memory (D2D, capturable).
    cudaMemcpyToSymbolAsync(c_w, w, F_OUT * 27 * sizeof(float), 0,
                            cudaMemcpyDeviceToDevice, 0);

    dim3 grid(HO / 2, NB, F_OUT / F_Q);   // (127, 16, 4)
    conv2dcq_kernel<<<grid, 128>>>(x, bias, out);
}

// round 11
// speedup vs baseline: 1.1285x; 1.1285x over previous
#include <cuda_runtime.h>
#include <cstdint>

// Degenerate conv (reference uses only x[:,0] and w[:,2]):
//   out(n,f,i,j) = bias[f] + sum_{a,b} w[f,2,a,b] * x[n,0,i+a,j+b]
//   x: (16,3,256,256) f32, w: (64,3,3,3) f32, b: (64,) f32
//   out: (16,64,254,254) f32
//
// Champion geometry (R9): 2x2 output patch per thread, warp-dense STG.64
// stores (256B contiguous, sector-aligned on every row). Grid (127,16,4):
// blockIdx.x = row-pair, .y = batch, .z = filter quarter; block = 128 threads
// = col-pair (zero div/mod). Weights in __constant__ (uniform LDC port, one
// CE staging node). This round: bias via 4 uniform LDG.128 with static
// component selection (16 -> 4 bias LSU ops), filter groups fully unrolled.
#define NB     16
#define F_OUT  64
#define F_Q    16
#define Hh     256
#define Ww     256
#define HO     254
#define WO     254
#define IP     (HO / 2)           // 127 row-pairs
#define JP     (WO / 2)           // 127 col-pairs

typedef unsigned long long u64;

__constant__ float c_w[F_OUT * 27];   // full weight tensor (we use [f][2][*])

// packed f32x2 FMA (Blackwell): d = a * w + c on both lanes
static __device__ __forceinline__ u64 ffma2(u64 a, u64 w, u64 c) {
    u64 d;
    asm("fma.rn.f32x2 %0, %1, %2, %3;" : "=l"(d) : "l"(a), "l"(w), "l"(c));
    return d;
}

static __device__ __forceinline__ u64 pack2(float lo, float hi) {
    u64 d;
    asm("mov.b64 %0, {%1, %2};" : "=l"(d) : "f"(lo), "f"(hi));
    return d;
}

__global__ __launch_bounds__(128) void conv2dcq_kernel(
    const float* __restrict__ x,
    const float* __restrict__ bias,
    float* __restrict__ out) {

    const int jp = threadIdx.x;           // 0..127 (127 live)
    if (jp >= JP) return;

    const int ip = blockIdx.x;            // 0..126
    const int n  = blockIdx.y;            // 0..15
    const int f0 = blockIdx.z * F_Q;      // 0,16,32,48 (block-uniform)

    const int i = ip * 2;
    const int j = jp * 2;

    // Input channel 0: 4 rows x 4 cols for a 2x2 output patch.
    const float* xb = x + (size_t)n * 3 * Hh * Ww + (size_t)i * Ww + j;

    // P[r][b] = (x[i+r][j+b], x[i+r][j+b+1]) packed f32x2
    u64 P[4][3];
    #pragma unroll
    for (int r = 0; r < 4; r++) {
        const float2 lo = *reinterpret_cast<const float2*>(xb + (size_t)r * Ww);
        const float2 hi = *reinterpret_cast<const float2*>(xb + (size_t)r * Ww + 2);
        P[r][0] = pack2(lo.x, lo.y);
        P[r][1] = pack2(lo.y, hi.x);
        P[r][2] = pack2(hi.x, hi.y);
    }

    float* ob = out + (size_t)n * F_OUT * HO * WO
                    + (size_t)f0 * HO * WO
                    + (size_t)i * WO + j;

    // bias for this quarter: 4 uniform LDG.128, one live per 4-filter group
    const float4* b4 = reinterpret_cast<const float4*>(bias + f0);

    #pragma unroll
    for (int g = 0; g < 4; g++) {
        const float4 bq = __ldg(b4 + g);            // uniform LDG.128
        const float bsel[4] = {bq.x, bq.y, bq.z, bq.w};   // static indexing only

        #pragma unroll
        for (int u = 0; u < 4; u++) {               // fully unrolled group
            const int f = f0 + g * 4 + u;
            const float* wf = c_w + f * 27 + 18;    // w[f,2,:,:], uniform LDC
            const float bv = bsel[u];               // compile-time select
            u64 a0 = pack2(bv, bv);
            u64 a1 = a0;

            #pragma unroll
            for (int a = 0; a < 3; a++) {
                #pragma unroll
                for (int b = 0; b < 3; b++) {
                    const float ws = wf[a * 3 + b]; // constant port
                    const u64 wp = pack2(ws, ws);
                    a0 = ffma2(P[a][b],     wp, a0);
                    a1 = ffma2(P[a + 1][b], wp, a1);
                }
            }

            // warp-dense, sector-aligned: consecutive threads -> consecutive
            // 8B; each warp store instruction writes one full 256B span.
            *reinterpret_cast<u64*>(ob)      = a0;
            *reinterpret_cast<u64*>(ob + WO) = a1;
            ob += (size_t)HO * WO;
        }
    }
}

extern "C" void kernel_launch(void* const* d_in, const int* in_sizes, int n_in,
                              void* d_out, int out_size) {
    const float* x    = (const float*)d_in[0];
    const float* w    = (const float*)d_in[1];
    const float* bias = (const float*)d_in[2];
    float* out        = (float*)d_out;

    // Single CE node: stage weights into constant memory (D2D, capturable).
    cudaMemcpyToSymbolAsync(c_w, w, F_OUT * 27 * sizeof(float), 0,
                            cudaMemcpyDeviceToDevice, 0);

    dim3 grid(IP, NB, F_OUT / F_Q);   // (127, 16, 4)
    conv2dcq_kernel<<<grid, 128>>>(x, bias, out);
}